// round 3
// baseline (speedup 1.0000x reference)
#include <cuda_runtime.h>

// TCL-without-parameters loss, GB300 sm_103a.
// score[b,c] = 0.5*||center_c||^2 - f_b . center_c   (0.5||f||^2 cancels in pos-neg)
// loss = mean relu(score[lab] + 5 - min_{c!=lab} score[c])

#define MARGIN_F 5.0f

constexpr int D      = 512;   // feature dim
constexpr int C      = 21;    // num classes
constexpr int TPB    = 64;    // threads per block
constexpr int RPT    = 2;     // rows per thread
constexpr int RPB    = TPB * RPT;        // 128 rows per block
constexpr int CHUNK  = 16;    // columns staged per chunk
constexpr int SROW   = CHUNK + 4;        // padded smem row stride (floats), 20*4=80B (16B aligned)
constexpr int NCHUNK = D / CHUNK;        // 32

__device__ float g_partials[4096];

__device__ __forceinline__ unsigned smem_u32(const void* p) {
    return (unsigned)__cvta_generic_to_shared(p);
}
__device__ __forceinline__ void cp16(void* s, const void* g) {
    asm volatile("cp.async.cg.shared.global [%0], [%1], 16;" :: "r"(smem_u32(s)), "l"(g));
}
__device__ __forceinline__ void cp_commit() { asm volatile("cp.async.commit_group;"); }
template <int N>
__device__ __forceinline__ void cp_wait() { asm volatile("cp.async.wait_group %0;" :: "n"(N)); }

// packed fp32x2 FMA (Blackwell): d = a*b + d, two independent fp32 lanes
__device__ __forceinline__ void fma2(unsigned long long& d, unsigned long long a, unsigned long long b) {
    asm("fma.rn.f32x2 %0, %1, %2, %0;" : "+l"(d) : "l"(a), "l"(b));
}

__global__ __launch_bounds__(TPB)
void tcl_main_kernel(const float* __restrict__ feat,
                     const float* __restrict__ centers,
                     const void* __restrict__ labels,
                     int B) {
    extern __shared__ float smem[];
    float* cen   = smem;                 // C*D floats (row-major, broadcast reads)
    float* c2    = cen + C * D;          // 32 floats (0.5*||c||^2)
    float* stage = c2 + 32;              // 2 * RPB * SROW floats, double-buffered feature tile

    const int tid  = threadIdx.x;
    const int row0 = blockIdx.x * RPB;

    __shared__ int lab_is_i64;

    // ---- prefetch chunk 0 (cp.async, coalesced: 4 threads x 16B per row-segment) ----
    {
        const float* src = feat + (size_t)row0 * D;
        #pragma unroll
        for (int i = 0; i < RPB * (CHUNK / 4) / TPB; i++) {   // 8 iters
            int idx = tid + i * TPB;
            int r   = idx / (CHUNK / 4);
            int c4  = idx % (CHUNK / 4);
            cp16(&stage[r * SROW + c4 * 4], src + (size_t)r * D + c4 * 4);
        }
        cp_commit();
    }

    // ---- label dtype sniff: int64 labels (<2^32) have all-zero odd int32 words.
    // For int32 labels, odd words are uniform in [0,21); P(64 all zero) ~ 21^-64.
    if (tid == 0) {
        const int* lw = (const int*)labels;
        int i64 = 1;
        #pragma unroll 8
        for (int i = 1; i < 128; i += 2)
            if (lw[i] != 0) { i64 = 0; break; }
        lab_is_i64 = i64;
    }

    // ---- load centers (L2-resident after first wave) ----
    for (int i = tid; i < C * D / 4; i += TPB)
        ((float4*)cen)[i] = ((const float4*)centers)[i];
    __syncthreads();

    // 0.5*||center_c||^2 (once per block, tiny)
    if (tid < C) {
        float s = 0.f;
        #pragma unroll 8
        for (int k = 0; k < D; k++) { float v = cen[tid * D + k]; s = fmaf(v, v, s); }
        c2[tid] = 0.5f * s;
    }

    // packed accumulators: acc[c][r] holds (even-col partial, odd-col partial)
    unsigned long long acc[C][RPT];
    #pragma unroll
    for (int c = 0; c < C; c++)
        #pragma unroll
        for (int r = 0; r < RPT; r++) acc[c][r] = 0ull;

    for (int ch = 0; ch < NCHUNK; ch++) {
        __syncthreads();   // everyone done reading the buffer we are about to overwrite
        if (ch + 1 < NCHUNK) {
            const float* src = feat + (size_t)row0 * D + (ch + 1) * CHUNK;
            float* dst = stage + ((ch + 1) & 1) * RPB * SROW;
            #pragma unroll
            for (int i = 0; i < RPB * (CHUNK / 4) / TPB; i++) {
                int idx = tid + i * TPB;
                int r   = idx / (CHUNK / 4);
                int c4  = idx % (CHUNK / 4);
                cp16(dst + r * SROW + c4 * 4, src + (size_t)r * D + c4 * 4);
            }
            cp_commit();
            cp_wait<1>();   // chunk ch has landed (only ch+1 may remain in flight)
        } else {
            cp_wait<0>();
        }
        __syncthreads();

        const float* buf = stage + (ch & 1) * RPB * SROW;
        const int kbase = ch * CHUNK;
        #pragma unroll
        for (int kk = 0; kk < CHUNK; kk += 4) {
            ulonglong2 f[RPT];
            #pragma unroll
            for (int r = 0; r < RPT; r++)
                f[r] = *(const ulonglong2*)&buf[(tid + r * TPB) * SROW + kk];   // own row, LDS.128
            const float* cc = cen + kbase + kk;
            #pragma unroll
            for (int c = 0; c < C; c++) {
                ulonglong2 cv = *(const ulonglong2*)&cc[c * D];  // broadcast LDS.128
                fma2(acc[c][0], f[0].x, cv.x);
                fma2(acc[c][0], f[0].y, cv.y);
                fma2(acc[c][1], f[1].x, cv.x);
                fma2(acc[c][1], f[1].y, cv.y);
            }
        }
    }

    // ---- epilogue: per-row margin loss ----
    const int use64 = lab_is_i64;   // uniform across block (set before first syncthreads)
    float local = 0.f;
    #pragma unroll
    for (int r = 0; r < RPT; r++) {
        int row = row0 + tid + r * TPB;
        int lab = use64 ? (int)((const long long*)labels)[row]
                        : ((const int*)labels)[row];
        float pos = 0.f, neg = 3.0e38f;
        #pragma unroll
        for (int c = 0; c < C; c++) {
            float lo = __uint_as_float((unsigned)(acc[c][r] & 0xffffffffu));
            float hi = __uint_as_float((unsigned)(acc[c][r] >> 32));
            float s  = c2[c] - (lo + hi);
            if (c == lab) pos = s;
            else          neg = fminf(neg, s);
        }
        local += fmaxf(0.f, pos + MARGIN_F - neg);
    }

    // ---- block reduce (2 warps) ----
    #pragma unroll
    for (int o = 16; o; o >>= 1) local += __shfl_down_sync(0xffffffffu, local, o);
    __shared__ float wsum[2];
    if ((tid & 31) == 0) wsum[tid >> 5] = local;
    __syncthreads();
    if (tid == 0) g_partials[blockIdx.x] = wsum[0] + wsum[1];
}

__global__ void tcl_reduce_kernel(float* __restrict__ out, int nblocks, float invB) {
    __shared__ float s[32];
    int tid = threadIdx.x;
    float v = 0.f;
    for (int i = tid; i < nblocks; i += blockDim.x) v += g_partials[i];
    #pragma unroll
    for (int o = 16; o; o >>= 1) v += __shfl_down_sync(0xffffffffu, v, o);
    if ((tid & 31) == 0) s[tid >> 5] = v;
    __syncthreads();
    if (tid < 32) {
        float w = (tid < (int)(blockDim.x + 31) / 32) ? s[tid] : 0.f;
        #pragma unroll
        for (int o = 16; o; o >>= 1) w += __shfl_down_sync(0xffffffffu, w, o);
        if (tid == 0) out[0] = w * invB;
    }
}

extern "C" void kernel_launch(void* const* d_in, const int* in_sizes, int n_in,
                              void* d_out, int out_size) {
    // Identify inputs by element count (robust to ordering):
    //   centers = C*D elements; labels = B; features = B*D.
    const float* cen = nullptr;
    for (int i = 0; i < n_in; i++)
        if (in_sizes[i] == C * D) cen = (const float*)d_in[i];

    int big = -1, small = -1;
    for (int i = 0; i < n_in; i++) {
        if ((const float*)d_in[i] == cen) continue;
        if (big < 0 || in_sizes[i] > in_sizes[big]) { small = big; big = i; }
        else small = i;
    }
    const float* feat = (const float*)d_in[big];
    const void*  lab  = d_in[small];
    int B = in_sizes[small];           // 65536

    int grid = B / RPB;                // 512

    size_t smem_bytes = (size_t)(C * D + 32 + 2 * RPB * SROW) * sizeof(float); // ~63.6 KB
    static int attr_set = 0;
    if (!attr_set) {
        cudaFuncSetAttribute(tcl_main_kernel, cudaFuncAttributeMaxDynamicSharedMemorySize,
                             (int)smem_bytes);
        attr_set = 1;
    }

    tcl_main_kernel<<<grid, TPB, smem_bytes>>>(feat, cen, lab, B);
    tcl_reduce_kernel<<<1, 512>>>((float*)d_out, grid, 1.0f / (float)B);
}